// round 10
// baseline (speedup 1.0000x reference)
#include <cuda_runtime.h>
#include <cuda_fp16.h>
#include <cstdint>

#define NB      16384
#define HDIM    64
#define SEQ     30
#define NMODE   3
#define MROWS   128
#define THREADS 256
#define NCTAS   384          // 49152 (elem,mode) rows / 128
#define STRH    88           // A row stride in halfs (44 words: conflict-free frags)
#define KS      5            // k-steps of 16 covering cols 0..79 (x16 | h64-permuted)
#define NT      32           // n-tiles of 8 gate-interleaved columns

// ---- SMEM float-unit offsets ----
#define OFF_BF  0                           // B frags: NT*KS*32 uint2 = 10240 floats
#define OFF_AH  (OFF_BF + NT * KS * 64)     // A halfs: 128*STRH = 11264 halfs = 5632 floats
#define OFF_BI  (OFF_AH + MROWS * STRH / 2) // [256] gate-interleaved bias
#define OFF_WP  (OFF_BI + 256)              // [64][2] interleaved (Wp0[u],Wp1[u])
#define OFF_WE  (OFF_WP + 128)              // [16][2]
#define OFF_BE  (OFF_WE + 32)               // [16]
#define OFF_BP  (OFF_BE + 16)               // [2] (+2 pad)
#define SMEM_FLOATS (OFF_BP + 4)
#define SMEM_BYTES  (SMEM_FLOATS * 4)       // ~65.3 KB -> 3 CTAs/SM

__device__ float g_hfin[NMODE * NB * HDIM];

// ============================ helpers ============================
__device__ __forceinline__ void mma16(float& d0, float& d1, float& d2, float& d3,
                                      uint32_t a0, uint32_t a1, uint32_t a2, uint32_t a3,
                                      uint32_t b0, uint32_t b1) {
    asm volatile("mma.sync.aligned.m16n8k16.row.col.f32.f16.f16.f32 "
                 "{%0,%1,%2,%3}, {%4,%5,%6,%7}, {%8,%9}, {%0,%1,%2,%3};"
                 : "+f"(d0), "+f"(d1), "+f"(d2), "+f"(d3)
                 : "r"(a0), "r"(a1), "r"(a2), "r"(a3), "r"(b0), "r"(b1));
}
__device__ __forceinline__ float tanha(float x) {
    float r; asm("tanh.approx.f32 %0, %1;" : "=f"(r) : "f"(x)); return r;
}
__device__ __forceinline__ float sigf(float x) {
    return fmaf(0.5f, tanha(0.5f * x), 0.5f);
}
__device__ __forceinline__ float lrelu_(float x) { return x > 0.0f ? x : 0.01f * x; }
__device__ __forceinline__ uint32_t packh2(float a, float b) {
    __half2 h = __floats2half2_rn(a, b);
    return *(uint32_t*)&h;
}

// gate-weight value for gate-row wr at A-col k (x 0..15 | permuted h 16..79)
// h permutation: col 16+j holds unit u = 2*(j&31) + (j>>5)
__device__ __forceinline__ float wval(const float* W_ih, const float* W_hh, int wr, int k) {
    if (k < 16) return W_ih[wr * 16 + k];
    const int j = k - 16;
    const int u = 2 * (j & 31) + (j >> 5);
    return W_hh[wr * 64 + u];
}

// ============================ main kernel ============================
__global__ void __launch_bounds__(THREADS, 3)
lstm_mma(const float* __restrict__ traj_rel, const float* __restrict__ h0,
         const float* __restrict__ c0,       const float* __restrict__ W_ih,
         const float* __restrict__ W_hh,     const float* __restrict__ b_ih,
         const float* __restrict__ b_hh,     const float* __restrict__ We,
         const float* __restrict__ be,       const float* __restrict__ Wp,
         const float* __restrict__ bp,       float* __restrict__ out)
{
    extern __shared__ float sm[];
    float*  sBF = sm + OFF_BF;
    __half* sAh = (__half*)(sm + OFF_AH);
    float*  sBI = sm + OFF_BI;
    float*  sWp = sm + OFF_WP;
    float*  sWe = sm + OFF_WE;
    float*  sbe = sm + OFF_BE;
    float*  sbp = sm + OFF_BP;

    const int tid  = threadIdx.x;
    const int w    = tid >> 5;
    const int lane = tid & 31;
    const int g    = lane >> 2;            // quad id (fragment row within m-tile)
    const int tig  = lane & 3;
    const int rA   = 16 * w + g;           // fragment rows rA / rA+8
    const int row  = rA + 8 * (tig & 1);   // the row this thread's epilogue owns
    const int usel = tig >> 1;             // unit parity this thread owns
    const int m    = blockIdx.x >> 7;
    const int e0   = (blockIdx.x & 127) * MROWS;

    // ---- prologue: B fragments (f16), fragment-major, k-permuted ----
    for (int idx = tid; idx < NT * KS * 32; idx += THREADS) {
        const int lane_ = idx & 31;
        const int rest  = idx >> 5;
        const int ks    = rest % KS, nt = rest / KS;
        const int n     = nt * 8 + (lane_ >> 2);
        const int k     = ks * 16 + 2 * (lane_ & 3);
        const int u     = n >> 2, gate = n & 3, wr = gate * 64 + u;
        float lo0 = wval(W_ih, W_hh, wr, k),     lo1 = wval(W_ih, W_hh, wr, k + 1);
        float hi0 = wval(W_ih, W_hh, wr, k + 8), hi1 = wval(W_ih, W_hh, wr, k + 9);
        ((uint2*)sBF)[idx] = make_uint2(packh2(lo0, lo1), packh2(hi0, hi1));
    }
    // ---- prologue: gate-interleaved bias; A = [x0 | h0-permuted] halfs ----
    if (tid < 256) {
        const int u = tid >> 2, gate = tid & 3, wr = gate * 64 + u;
        sBI[tid] = b_ih[wr] + b_hh[wr];
    }
    for (int idx = tid; idx < MROWS * 80; idx += THREADS) {
        const int r = idx / 80, k = idx - r * 80;
        float v;
        if (k < 16) {
            float t0 = traj_rel[(e0 + r) * 2 + 0];
            float t1 = traj_rel[(e0 + r) * 2 + 1];
            v = lrelu_(t0 * We[k * 2 + 0] + t1 * We[k * 2 + 1] + be[k]);
        } else {
            const int j = k - 16;
            v = h0[(e0 + r) * HDIM + 2 * (j & 31) + (j >> 5)];
        }
        sAh[r * STRH + k] = __float2half_rn(v);
    }
    // Wp interleaved: sWp[u*2 + d] = Wp[m][d][u]
    if (tid < 128) sWp[tid] = Wp[m * 128 + (tid & 1) * 64 + (tid >> 1)];
    if (tid < 32)  sWe[tid] = We[tid];
    if (tid < 16)  sbe[tid] = be[tid];
    if (tid < 2)   sbp[tid] = bp[m * 2 + tid];

    // per-thread cell state: (row, unit = 2*nt + usel)
    float c[NT];
    #pragma unroll
    for (int nt = 0; nt < NT; nt++)
        c[nt] = c0[(e0 + row) * HDIM + 2 * nt + usel];

    __syncthreads();      // one-time: prologue visible to all warps

    const float bp0 = sbp[0], bp1 = sbp[1];

    // persistent fragments: af[0] = x-frag (registers across iterations)
    uint32_t af[KS][4];
    af[0][0] = *(const uint32_t*)(sAh + rA * STRH + 2 * tig);
    af[0][1] = *(const uint32_t*)(sAh + (rA + 8) * STRH + 2 * tig);
    af[0][2] = *(const uint32_t*)(sAh + rA * STRH + 2 * tig + 8);
    af[0][3] = *(const uint32_t*)(sAh + (rA + 8) * STRH + 2 * tig + 8);

    for (int t = 0; t < SEQ; t++) {
        // ---- load h fragments (ks = 1..4) from own warp's rows ----
        #pragma unroll
        for (int ks = 1; ks < KS; ks++) {
            const int k0 = ks * 16 + 2 * tig;
            af[ks][0] = *(const uint32_t*)(sAh + rA * STRH + k0);
            af[ks][1] = *(const uint32_t*)(sAh + (rA + 8) * STRH + k0);
            af[ks][2] = *(const uint32_t*)(sAh + rA * STRH + k0 + 8);
            af[ks][3] = *(const uint32_t*)(sAh + (rA + 8) * STRH + k0 + 8);
        }
        __syncwarp();   // loads complete before this iteration's h stores

        float p0 = 0.0f, p1 = 0.0f;

        // ---- n-tiles in groups of 4: 4 independent accumulator chains ----
        #pragma unroll
        for (int nt4 = 0; nt4 < NT / 4; nt4++) {
            float d[4][4];
            #pragma unroll
            for (int i = 0; i < 4; i++) {
                const float2 bv = *(const float2*)(sBI + (nt4 * 4 + i) * 8 + 2 * tig);
                d[i][0] = bv.x; d[i][1] = bv.y; d[i][2] = bv.x; d[i][3] = bv.y;
            }
            const uint2* bf = (const uint2*)sBF + (nt4 * 4 * KS) * 32 + lane;
            #pragma unroll
            for (int ks = 0; ks < KS; ks++) {
                #pragma unroll
                for (int i = 0; i < 4; i++) {
                    const uint2 bv = bf[(i * KS + ks) * 32];
                    mma16(d[i][0], d[i][1], d[i][2], d[i][3],
                          af[ks][0], af[ks][1], af[ks][2], af[ks][3],
                          bv.x, bv.y);
                }
            }
            // ---- epilogue for the four tiles ----
            float hpair[4];
            #pragma unroll
            for (int i = 0; i < 4; i++) {
                const int nt = nt4 * 4 + i;
                const float d0 = d[i][0], d1 = d[i][1], d2 = d[i][2], d3 = d[i][3];
                const bool  odd = tig & 1;
                const float s0 = odd ? d0 : d2;
                const float s1 = odd ? d1 : d3;
                const float q0 = __shfl_xor_sync(0xffffffffu, s0, 1);
                const float q1 = __shfl_xor_sync(0xffffffffu, s1, 1);
                const float gi = odd ? q0 : d0;
                const float gf = odd ? q1 : d1;
                const float gg = odd ? d2 : q0;
                const float go = odd ? d3 : q1;
                const float iv = sigf(gi);
                const float fv = sigf(gf);
                const float gv = tanha(gg);
                const float ov = sigf(go);
                const float cn = fv * c[nt] + iv * gv;
                c[nt] = cn;
                const float h = ov * tanha(cn);
                const int   u = 2 * nt + usel;
                const float2 wp2 = *(const float2*)(sWp + u * 2);
                p0 += h * wp2.x;
                p1 += h * wp2.y;
                hpair[i] = h;
                if (t == SEQ - 1)
                    g_hfin[(m * NB + e0 + row) * HDIM + u] = h;
            }
            // h writeback for this group: one STS.64 (cols 16+32*usel+nt4*4 .. +3)
            *(uint2*)(sAh + row * STRH + 16 + 32 * usel + nt4 * 4) =
                make_uint2(packh2(hpair[0], hpair[1]), packh2(hpair[2], hpair[3]));
        }

        // ---- rel_pos + next x fragment, all in-warp ----
        p0 += __shfl_xor_sync(0xffffffffu, p0, 2);
        p1 += __shfl_xor_sync(0xffffffffu, p1, 2);
        const float v0a = __shfl_sync(0xffffffffu, p0, 4 * g);
        const float v1a = __shfl_sync(0xffffffffu, p1, 4 * g);
        const float v0b = __shfl_sync(0xffffffffu, p0, 4 * g + 1);
        const float v1b = __shfl_sync(0xffffffffu, p1, 4 * g + 1);
        const float ra0 = v0a + bp0, ra1 = v1a + bp1;   // rel_pos(rA)
        const float rb0 = v0b + bp0, rb1 = v1b + bp1;   // rel_pos(rA+8)
        if (tig < 2) {
            float2 rv = tig ? make_float2(rb0, rb1) : make_float2(ra0, ra1);
            *(float2*)(out + (size_t)(e0 + rA + 8 * tig) * (NMODE * SEQ * 2)
                           + m * (SEQ * 2) + t * 2) = rv;
        }
        // next x fragment: cols 2tig,2tig+1 (lo) and +8 (hi) for rows rA, rA+8
        {
            const int k0 = 2 * tig;
            #pragma unroll
            for (int hh = 0; hh < 2; hh++) {
                const int ka = k0 + 8 * hh, kb = ka + 1;
                const float xa0 = lrelu_(fmaf(ra0, sWe[ka * 2], fmaf(ra1, sWe[ka * 2 + 1], sbe[ka])));
                const float xa1 = lrelu_(fmaf(ra0, sWe[kb * 2], fmaf(ra1, sWe[kb * 2 + 1], sbe[kb])));
                const float xb0 = lrelu_(fmaf(rb0, sWe[ka * 2], fmaf(rb1, sWe[ka * 2 + 1], sbe[ka])));
                const float xb1 = lrelu_(fmaf(rb0, sWe[kb * 2], fmaf(rb1, sWe[kb * 2 + 1], sbe[kb])));
                af[0][0 + hh * 2] = packh2(xa0, xa1);
                af[0][1 + hh * 2] = packh2(xb0, xb1);
            }
        }
        __syncwarp();   // h stores visible before next iteration's loads
    }
}

// ============================ confidence kernel ============================
#define CONF_EPW 2
__global__ void __launch_bounds__(256)
conf_kernel(const float* __restrict__ Wc,
            const float* __restrict__ bc,
            float* __restrict__ out)
{
    const int warp  = (blockIdx.x * blockDim.x + threadIdx.x) >> 5;
    const int lane  = threadIdx.x & 31;
    const int ebase = warp * CONF_EPW;

    for (int ei = 0; ei < CONF_EPW; ei++) {
        const int e = ebase + ei;
        float l0 = 0.f, l1 = 0.f, l2 = 0.f;
        #pragma unroll
        for (int i = 0; i < 12; i++) {
            const int k = lane + 32 * i;
            if (k < 372) {
                const int q = (k >= 248) ? 2 : (k >= 124 ? 1 : 0);
                const int r = k - q * 124;
                const float v = (r < 60)
                    ? out[e * (NMODE * SEQ * 2) + q * 60 + r]
                    : g_hfin[(q * NB + e) * HDIM + (r - 60)];
                l0 += Wc[0 * 372 + k] * v;
                l1 += Wc[1 * 372 + k] * v;
                l2 += Wc[2 * 372 + k] * v;
            }
        }
        #pragma unroll
        for (int s = 16; s > 0; s >>= 1) {
            l0 += __shfl_xor_sync(0xffffffffu, l0, s);
            l1 += __shfl_xor_sync(0xffffffffu, l1, s);
            l2 += __shfl_xor_sync(0xffffffffu, l2, s);
        }
        if (lane == 0) {
            l0 += bc[0]; l1 += bc[1]; l2 += bc[2];
            const float mx = fmaxf(l0, fmaxf(l1, l2));
            const float x0 = __expf(l0 - mx), x1 = __expf(l1 - mx), x2 = __expf(l2 - mx);
            const float inv = __fdividef(1.0f, x0 + x1 + x2);
            float* cf = out + NB * (NMODE * SEQ * 2) + e * NMODE;
            cf[0] = x0 * inv; cf[1] = x1 * inv; cf[2] = x2 * inv;
        }
    }
}

extern "C" void kernel_launch(void* const* d_in, const int* in_sizes, int n_in,
                              void* d_out, int out_size)
{
    const float* traj_rel = (const float*)d_in[1];
    const float* h0   = (const float*)d_in[2];
    const float* c0   = (const float*)d_in[3];
    const float* W_ih = (const float*)d_in[4];
    const float* W_hh = (const float*)d_in[5];
    const float* b_ih = (const float*)d_in[6];
    const float* b_hh = (const float*)d_in[7];
    const float* We   = (const float*)d_in[8];
    const float* be   = (const float*)d_in[9];
    const float* Wp   = (const float*)d_in[10];
    const float* bp   = (const float*)d_in[11];
    const float* Wc   = (const float*)d_in[12];
    const float* bc   = (const float*)d_in[13];
    float* out = (float*)d_out;

    cudaFuncSetAttribute(lstm_mma,
                         cudaFuncAttributeMaxDynamicSharedMemorySize, SMEM_BYTES);

    lstm_mma<<<NCTAS, THREADS, SMEM_BYTES>>>(traj_rel, h0, c0, W_ih, W_hh,
                                             b_ih, b_hh, We, be, Wp, bp, out);
    conf_kernel<<<NB / (CONF_EPW * 8), 256>>>(Wc, bc, out);
}

// round 11
// speedup vs baseline: 1.0804x; 1.0804x over previous
#include <cuda_runtime.h>
#include <cuda_fp16.h>
#include <cstdint>

#define NB      16384
#define HDIM    64
#define SEQ     30
#define NMODE   3
#define MROWS   128
#define THREADS 256
#define NCTAS   384          // 49152 (elem,mode) rows / 128
#define STRH    88           // A row stride in halfs
#define KS      5            // k-steps of 16 covering cols 0..79 (x16 | h64-permuted)
#define NT      32           // n-tiles of 8 columns

// ---- SMEM float-unit offsets ----
#define OFF_BF  0                           // B frags: NT*KS*32 uint2 = 10240 floats
#define OFF_AH  (OFF_BF + NT * KS * 64)     // A halfs: 128*STRH = 11264 halfs = 5632 floats
#define OFF_BI  (OFF_AH + MROWS * STRH / 2) // [256] column-order bias
#define OFF_WP  (OFF_BI + 256)              // [64][2] interleaved (Wp0[u],Wp1[u])
#define OFF_WE  (OFF_WP + 128)              // [16][2]
#define OFF_BE  (OFF_WE + 32)               // [16]
#define OFF_BP  (OFF_BE + 16)               // [2] (+2 pad)
#define SMEM_FLOATS (OFF_BP + 4)
#define SMEM_BYTES  (SMEM_FLOATS * 4)       // ~65.3 KB -> 2 CTAs/SM

__device__ float g_hfin[NMODE * NB * HDIM];

// ============================ helpers ============================
__device__ __forceinline__ void mma16(float& d0, float& d1, float& d2, float& d3,
                                      uint32_t a0, uint32_t a1, uint32_t a2, uint32_t a3,
                                      uint32_t b0, uint32_t b1) {
    asm volatile("mma.sync.aligned.m16n8k16.row.col.f32.f16.f16.f32 "
                 "{%0,%1,%2,%3}, {%4,%5,%6,%7}, {%8,%9}, {%0,%1,%2,%3};"
                 : "+f"(d0), "+f"(d1), "+f"(d2), "+f"(d3)
                 : "r"(a0), "r"(a1), "r"(a2), "r"(a3), "r"(b0), "r"(b1));
}
__device__ __forceinline__ float tanha(float x) {
    float r; asm("tanh.approx.f32 %0, %1;" : "=f"(r) : "f"(x)); return r;
}
__device__ __forceinline__ float sigf(float x) {
    return fmaf(0.5f, tanha(0.5f * x), 0.5f);
}
__device__ __forceinline__ float lrelu_(float x) { return x > 0.0f ? x : 0.01f * x; }
__device__ __forceinline__ uint32_t packh2(float a, float b) {
    __half2 h = __floats2half2_rn(a, b);
    return *(uint32_t*)&h;
}

// B column n -> original gate-matrix row.
// Tiles 0..15 (n<128): tile q=n>>3, local l=n&7: gate s=l&1 (0:i,1:f), unit 4q+(l>>1).
// Tiles 16..31 (n>=128): same but gates (g,o).
__device__ __forceinline__ int col2wr(int n) {
    const int half = n >> 7, nn = n & 127;
    const int q = nn >> 3, l = nn & 7;
    return half * 128 + (l & 1) * 64 + 4 * q + (l >> 1);
}
// gate-weight value for gate-row wr at A-col k (x 0..15 | permuted h 16..79)
// h permutation: col 16+j holds unit u = 4*(j&15) + (j>>4)
__device__ __forceinline__ float wval(const float* W_ih, const float* W_hh, int wr, int k) {
    if (k < 16) return W_ih[wr * 16 + k];
    const int j = k - 16;
    return W_hh[wr * 64 + 4 * (j & 15) + (j >> 4)];
}

// ============================ main kernel ============================
__global__ void __launch_bounds__(THREADS, 2)
lstm_mma(const float* __restrict__ traj_rel, const float* __restrict__ h0,
         const float* __restrict__ c0,       const float* __restrict__ W_ih,
         const float* __restrict__ W_hh,     const float* __restrict__ b_ih,
         const float* __restrict__ b_hh,     const float* __restrict__ We,
         const float* __restrict__ be,       const float* __restrict__ Wp,
         const float* __restrict__ bp,       float* __restrict__ out)
{
    extern __shared__ float sm[];
    float*  sBF = sm + OFF_BF;
    __half* sAh = (__half*)(sm + OFF_AH);
    float*  sBI = sm + OFF_BI;
    float*  sWp = sm + OFF_WP;
    float*  sWe = sm + OFF_WE;
    float*  sbe = sm + OFF_BE;
    float*  sbp = sm + OFF_BP;

    const int tid  = threadIdx.x;
    const int w    = tid >> 5;
    const int lane = tid & 31;
    const int g    = lane >> 2;            // quad id (fragment row within m-tile)
    const int tig  = lane & 3;
    const int rA   = 16 * w + g;           // this thread owns rows rA and rA+8
    const int m    = blockIdx.x >> 7;
    const int e0   = (blockIdx.x & 127) * MROWS;

    // ---- prologue: B fragments (f16), fragment-major, new column mapping ----
    for (int idx = tid; idx < NT * KS * 32; idx += THREADS) {
        const int lane_ = idx & 31;
        const int rest  = idx >> 5;
        const int ks    = rest % KS, nt = rest / KS;
        const int n     = nt * 8 + (lane_ >> 2);
        const int k     = ks * 16 + 2 * (lane_ & 3);
        const int wr    = col2wr(n);
        float lo0 = wval(W_ih, W_hh, wr, k),     lo1 = wval(W_ih, W_hh, wr, k + 1);
        float hi0 = wval(W_ih, W_hh, wr, k + 8), hi1 = wval(W_ih, W_hh, wr, k + 9);
        ((uint2*)sBF)[idx] = make_uint2(packh2(lo0, lo1), packh2(hi0, hi1));
    }
    // ---- prologue: column-order bias; A = [x0 | h0-permuted] halfs ----
    if (tid < 256) {
        const int wr = col2wr(tid);
        sBI[tid] = b_ih[wr] + b_hh[wr];
    }
    for (int idx = tid; idx < MROWS * 80; idx += THREADS) {
        const int r = idx / 80, k = idx - r * 80;
        float v;
        if (k < 16) {
            float t0 = traj_rel[(e0 + r) * 2 + 0];
            float t1 = traj_rel[(e0 + r) * 2 + 1];
            v = lrelu_(t0 * We[k * 2 + 0] + t1 * We[k * 2 + 1] + be[k]);
        } else {
            const int j = k - 16;
            v = h0[(e0 + r) * HDIM + 4 * (j & 15) + (j >> 4)];
        }
        sAh[r * STRH + k] = __float2half_rn(v);
    }
    // Wp interleaved: sWp[u*2 + d] = Wp[m][d][u]
    if (tid < 128) sWp[tid] = Wp[m * 128 + (tid & 1) * 64 + (tid >> 1)];
    if (tid < 32)  sWe[tid] = We[tid];
    if (tid < 16)  sbe[tid] = be[tid];
    if (tid < 2)   sbp[tid] = bp[m * 2 + tid];

    // per-thread cell state: rows rA / rA+8, units u = 4q + tig, q = 0..15
    float ca[16], cb[16];
    #pragma unroll
    for (int q = 0; q < 16; q++) {
        ca[q] = c0[(e0 + rA) * HDIM + 4 * q + tig];
        cb[q] = c0[(e0 + rA + 8) * HDIM + 4 * q + tig];
    }

    __syncthreads();      // one-time: prologue visible to all warps

    const float bp0 = sbp[0], bp1 = sbp[1];

    // persistent fragments: af[0] = x-frag (registers across iterations)
    uint32_t af[KS][4];
    af[0][0] = *(const uint32_t*)(sAh + rA * STRH + 2 * tig);
    af[0][1] = *(const uint32_t*)(sAh + (rA + 8) * STRH + 2 * tig);
    af[0][2] = *(const uint32_t*)(sAh + rA * STRH + 2 * tig + 8);
    af[0][3] = *(const uint32_t*)(sAh + (rA + 8) * STRH + 2 * tig + 8);

    for (int t = 0; t < SEQ; t++) {
        // ---- load h fragments (ks = 1..4) from own warp's rows ----
        #pragma unroll
        for (int ks = 1; ks < KS; ks++) {
            const int k0 = ks * 16 + 2 * tig;
            af[ks][0] = *(const uint32_t*)(sAh + rA * STRH + k0);
            af[ks][1] = *(const uint32_t*)(sAh + (rA + 8) * STRH + k0);
            af[ks][2] = *(const uint32_t*)(sAh + rA * STRH + k0 + 8);
            af[ks][3] = *(const uint32_t*)(sAh + (rA + 8) * STRH + k0 + 8);
        }
        __syncwarp();   // loads complete before this iteration's h stores

        float p0a = 0.f, p1a = 0.f, p0b = 0.f, p1b = 0.f;

        // ---- 8 groups: tiles {2qq, 2qq+1, 16+2qq, 17+2qq} = 4 chains ----
        #pragma unroll
        for (int qq = 0; qq < 8; qq++) {
            const int T0 = 2 * qq;          // (i,f) tiles T0, T0+1 ; (g,o) tiles 16+T0, 17+T0
            float d[4][4];
            #pragma unroll
            for (int i = 0; i < 4; i++) {
                const int T = (i < 2) ? (T0 + i) : (16 + T0 + (i - 2));
                const float2 bv = *(const float2*)(sBI + T * 8 + 2 * tig);
                d[i][0] = bv.x; d[i][1] = bv.y; d[i][2] = bv.x; d[i][3] = bv.y;
            }
            #pragma unroll
            for (int ks = 0; ks < KS; ks++) {
                #pragma unroll
                for (int i = 0; i < 4; i++) {
                    const int T = (i < 2) ? (T0 + i) : (16 + T0 + (i - 2));
                    const uint2 bv = ((const uint2*)sBF)[(T * KS + ks) * 32 + lane];
                    mma16(d[i][0], d[i][1], d[i][2], d[i][3],
                          af[ks][0], af[ks][1], af[ks][2], af[ks][3],
                          bv.x, bv.y);
                }
            }
            // ---- epilogue: units u = 4*(2qq+j)+tig, rows rA and rA+8, no shfl ----
            float ha[2], hb[2];
            #pragma unroll
            for (int j = 0; j < 2; j++) {
                const int qi = 2 * qq + j;
                const int u  = 4 * qi + tig;
                const float2 wp2 = *(const float2*)(sWp + u * 2);
                // row rA: d[j] = (i,f), d[2+j] = (g,o), lanes 0,1
                {
                    const float iv = sigf(d[j][0]);
                    const float fv = sigf(d[j][1]);
                    const float gv = tanha(d[2 + j][0]);
                    const float ov = sigf(d[2 + j][1]);
                    const float cn = fv * ca[qi] + iv * gv;
                    ca[qi] = cn;
                    const float h = ov * tanha(cn);
                    ha[j] = h;
                    p0a += h * wp2.x; p1a += h * wp2.y;
                }
                // row rA+8: lanes 2,3
                {
                    const float iv = sigf(d[j][2]);
                    const float fv = sigf(d[j][3]);
                    const float gv = tanha(d[2 + j][2]);
                    const float ov = sigf(d[2 + j][3]);
                    const float cn = fv * cb[qi] + iv * gv;
                    cb[qi] = cn;
                    const float h = ov * tanha(cn);
                    hb[j] = h;
                    p0b += h * wp2.x; p1b += h * wp2.y;
                }
                if (t == SEQ - 1) {
                    g_hfin[(m * NB + e0 + rA) * HDIM + u]     = ha[j];
                    g_hfin[(m * NB + e0 + rA + 8) * HDIM + u] = hb[j];
                }
            }
            // h writeback: unit 4qi+tig -> col 16 + 16*tig + qi  (pairs qi=2qq,2qq+1)
            *(uint32_t*)(sAh + rA * STRH + 16 + 16 * tig + 2 * qq)       = packh2(ha[0], ha[1]);
            *(uint32_t*)(sAh + (rA + 8) * STRH + 16 + 16 * tig + 2 * qq) = packh2(hb[0], hb[1]);
        }

        // ---- rel_pos: reduce over tig within quad (units partition) ----
        p0a += __shfl_xor_sync(0xffffffffu, p0a, 1);
        p0a += __shfl_xor_sync(0xffffffffu, p0a, 2);
        p1a += __shfl_xor_sync(0xffffffffu, p1a, 1);
        p1a += __shfl_xor_sync(0xffffffffu, p1a, 2);
        p0b += __shfl_xor_sync(0xffffffffu, p0b, 1);
        p0b += __shfl_xor_sync(0xffffffffu, p0b, 2);
        p1b += __shfl_xor_sync(0xffffffffu, p1b, 1);
        p1b += __shfl_xor_sync(0xffffffffu, p1b, 2);
        const float ra0 = p0a + bp0, ra1 = p1a + bp1;   // rel_pos(rA)
        const float rb0 = p0b + bp0, rb1 = p1b + bp1;   // rel_pos(rA+8)
        if (tig < 2) {
            float2 rv = tig ? make_float2(rb0, rb1) : make_float2(ra0, ra1);
            *(float2*)(out + (size_t)(e0 + rA + 8 * tig) * (NMODE * SEQ * 2)
                           + m * (SEQ * 2) + t * 2) = rv;
        }
        // next x fragment: cols 2tig,2tig+1 (lo) and +8 (hi) for rows rA, rA+8
        {
            const int k0 = 2 * tig;
            #pragma unroll
            for (int hh = 0; hh < 2; hh++) {
                const int ka = k0 + 8 * hh, kb = ka + 1;
                const float xa0 = lrelu_(fmaf(ra0, sWe[ka * 2], fmaf(ra1, sWe[ka * 2 + 1], sbe[ka])));
                const float xa1 = lrelu_(fmaf(ra0, sWe[kb * 2], fmaf(ra1, sWe[kb * 2 + 1], sbe[kb])));
                const float xb0 = lrelu_(fmaf(rb0, sWe[ka * 2], fmaf(rb1, sWe[ka * 2 + 1], sbe[ka])));
                const float xb1 = lrelu_(fmaf(rb0, sWe[kb * 2], fmaf(rb1, sWe[kb * 2 + 1], sbe[kb])));
                af[0][0 + hh * 2] = packh2(xa0, xa1);
                af[0][1 + hh * 2] = packh2(xb0, xb1);
            }
        }
        __syncwarp();   // h stores visible before next iteration's loads
    }
}

// ============================ confidence kernel ============================
#define CONF_EPW 2
__global__ void __launch_bounds__(256)
conf_kernel(const float* __restrict__ Wc,
            const float* __restrict__ bc,
            float* __restrict__ out)
{
    const int warp  = (blockIdx.x * blockDim.x + threadIdx.x) >> 5;
    const int lane  = threadIdx.x & 31;
    const int ebase = warp * CONF_EPW;

    for (int ei = 0; ei < CONF_EPW; ei++) {
        const int e = ebase + ei;
        float l0 = 0.f, l1 = 0.f, l2 = 0.f;
        #pragma unroll
        for (int i = 0; i < 12; i++) {
            const int k = lane + 32 * i;
            if (k < 372) {
                const int q = (k >= 248) ? 2 : (k >= 124 ? 1 : 0);
                const int r = k - q * 124;
                const float v = (r < 60)
                    ? out[e * (NMODE * SEQ * 2) + q * 60 + r]
                    : g_hfin[(q * NB + e) * HDIM + (r - 60)];
                l0 += Wc[0 * 372 + k] * v;
                l1 += Wc[1 * 372 + k] * v;
                l2 += Wc[2 * 372 + k] * v;
            }
        }
        #pragma unroll
        for (int s = 16; s > 0; s >>= 1) {
            l0 += __shfl_xor_sync(0xffffffffu, l0, s);
            l1 += __shfl_xor_sync(0xffffffffu, l1, s);
            l2 += __shfl_xor_sync(0xffffffffu, l2, s);
        }
        if (lane == 0) {
            l0 += bc[0]; l1 += bc[1]; l2 += bc[2];
            const float mx = fmaxf(l0, fmaxf(l1, l2));
            const float x0 = __expf(l0 - mx), x1 = __expf(l1 - mx), x2 = __expf(l2 - mx);
            const float inv = __fdividef(1.0f, x0 + x1 + x2);
            float* cf = out + NB * (NMODE * SEQ * 2) + e * NMODE;
            cf[0] = x0 * inv; cf[1] = x1 * inv; cf[2] = x2 * inv;
        }
    }
}

extern "C" void kernel_launch(void* const* d_in, const int* in_sizes, int n_in,
                              void* d_out, int out_size)
{
    const float* traj_rel = (const float*)d_in[1];
    const float* h0   = (const float*)d_in[2];
    const float* c0   = (const float*)d_in[3];
    const float* W_ih = (const float*)d_in[4];
    const float* W_hh = (const float*)d_in[5];
    const float* b_ih = (const float*)d_in[6];
    const float* b_hh = (const float*)d_in[7];
    const float* We   = (const float*)d_in[8];
    const float* be   = (const float*)d_in[9];
    const float* Wp   = (const float*)d_in[10];
    const float* bp   = (const float*)d_in[11];
    const float* Wc   = (const float*)d_in[12];
    const float* bc   = (const float*)d_in[13];
    float* out = (float*)d_out;

    cudaFuncSetAttribute(lstm_mma,
                         cudaFuncAttributeMaxDynamicSharedMemorySize, SMEM_BYTES);

    lstm_mma<<<NCTAS, THREADS, SMEM_BYTES>>>(traj_rel, h0, c0, W_ih, W_hh,
                                             b_ih, b_hh, We, be, Wp, bp, out);
    conf_kernel<<<NB / (CONF_EPW * 8), 256>>>(Wc, bc, out);
}

// round 12
// speedup vs baseline: 1.0876x; 1.0067x over previous
#include <cuda_runtime.h>
#include <cuda_fp16.h>
#include <cstdint>

#define NB      16384
#define HDIM    64
#define SEQ     30
#define NMODE   3
#define MROWS   128
#define THREADS 256
#define NCTAS   384          // 49152 (elem,mode) rows / 128
#define STRH    88           // A row stride in halfs
#define KS      5            // k-steps of 16 covering cols 0..79 (x16 | h64-permuted)
#define NT      32           // n-tiles of 8 columns
#define NBF     (NT * KS * 32)   // 5120 B-fragment entries (uint2)

// ---- SMEM float-unit offsets ----
#define OFF_BF  0                           // B frags: NBF uint2 = 10240 floats
#define OFF_AH  (OFF_BF + NBF * 2)          // A halfs: 128*STRH = 11264 halfs = 5632 floats
#define OFF_BI  (OFF_AH + MROWS * STRH / 2) // [256] column-order bias
#define OFF_WP  (OFF_BI + 256)              // [64][2] interleaved (Wp0[u],Wp1[u])
#define OFF_WE  (OFF_WP + 128)              // [16][2]
#define OFF_BE  (OFF_WE + 32)               // [16]
#define OFF_BP  (OFF_BE + 16)               // [2] (+2 pad)
#define SMEM_FLOATS (OFF_BP + 4)
#define SMEM_BYTES  (SMEM_FLOATS * 4)       // ~65.3 KB -> 3 CTAs/SM

__device__ float g_hfin[NMODE * NB * HDIM];
__device__ uint2 g_bfrag[NBF];              // precomputed f16 B fragments
__device__ float g_bias[256];               // precomputed column-order bias

// ============================ helpers ============================
__device__ __forceinline__ void mma16(float& d0, float& d1, float& d2, float& d3,
                                      uint32_t a0, uint32_t a1, uint32_t a2, uint32_t a3,
                                      uint32_t b0, uint32_t b1) {
    asm volatile("mma.sync.aligned.m16n8k16.row.col.f32.f16.f16.f32 "
                 "{%0,%1,%2,%3}, {%4,%5,%6,%7}, {%8,%9}, {%0,%1,%2,%3};"
                 : "+f"(d0), "+f"(d1), "+f"(d2), "+f"(d3)
                 : "r"(a0), "r"(a1), "r"(a2), "r"(a3), "r"(b0), "r"(b1));
}
__device__ __forceinline__ float tanha(float x) {
    float r; asm("tanh.approx.f32 %0, %1;" : "=f"(r) : "f"(x)); return r;
}
__device__ __forceinline__ float sigf(float x) {
    return fmaf(0.5f, tanha(0.5f * x), 0.5f);
}
__device__ __forceinline__ float lrelu_(float x) { return x > 0.0f ? x : 0.01f * x; }
__device__ __forceinline__ uint32_t packh2(float a, float b) {
    __half2 h = __floats2half2_rn(a, b);
    return *(uint32_t*)&h;
}

// B column n -> original gate-matrix row.
// Tiles 0..15: (i,f) pairs; tiles 16..31: (g,o). local l: gate s=l&1, unit 4q+(l>>1).
__device__ __forceinline__ int col2wr(int n) {
    const int half = n >> 7, nn = n & 127;
    const int q = nn >> 3, l = nn & 7;
    return half * 128 + (l & 1) * 64 + 4 * q + (l >> 1);
}
// gate-weight value for gate-row wr at A-col k (x 0..15 | permuted h 16..79)
// h permutation: col 16+j holds unit u = 4*(j&15) + (j>>4)
__device__ __forceinline__ float wval(const float* W_ih, const float* W_hh, int wr, int k) {
    if (k < 16) return W_ih[wr * 16 + k];
    const int j = k - 16;
    return W_hh[wr * 64 + 4 * (j & 15) + (j >> 4)];
}

// ============================ setup kernel: B frags + bias (once) ============================
__global__ void __launch_bounds__(256)
prep_b(const float* __restrict__ W_ih, const float* __restrict__ W_hh,
       const float* __restrict__ b_ih, const float* __restrict__ b_hh)
{
    const int idx = blockIdx.x * 256 + threadIdx.x;
    if (idx < NBF) {
        const int lane_ = idx & 31;
        const int rest  = idx >> 5;
        const int ks    = rest % KS, nt = rest / KS;
        const int n     = nt * 8 + (lane_ >> 2);
        const int k     = ks * 16 + 2 * (lane_ & 3);
        const int wr    = col2wr(n);
        float lo0 = wval(W_ih, W_hh, wr, k),     lo1 = wval(W_ih, W_hh, wr, k + 1);
        float hi0 = wval(W_ih, W_hh, wr, k + 8), hi1 = wval(W_ih, W_hh, wr, k + 9);
        g_bfrag[idx] = make_uint2(packh2(lo0, lo1), packh2(hi0, hi1));
    }
    if (idx < 256) {
        const int wr = col2wr(idx);
        g_bias[idx] = b_ih[wr] + b_hh[wr];
    }
}

// ============================ main kernel ============================
__global__ void __launch_bounds__(THREADS, 3)
lstm_mma(const float* __restrict__ traj_rel, const float* __restrict__ h0,
         const float* __restrict__ c0,       const float* __restrict__ We,
         const float* __restrict__ be,       const float* __restrict__ Wp,
         const float* __restrict__ bp,       float* __restrict__ out)
{
    extern __shared__ float sm[];
    float*  sBF = sm + OFF_BF;
    __half* sAh = (__half*)(sm + OFF_AH);
    float*  sBI = sm + OFF_BI;
    float*  sWp = sm + OFF_WP;
    float*  sWe = sm + OFF_WE;
    float*  sbe = sm + OFF_BE;
    float*  sbp = sm + OFF_BP;

    const int tid  = threadIdx.x;
    const int w    = tid >> 5;
    const int lane = tid & 31;
    const int g    = lane >> 2;            // quad id (fragment row within m-tile)
    const int tig  = lane & 3;
    const int rA   = 16 * w + g;           // this thread owns rows rA and rA+8
    const int m    = blockIdx.x >> 7;
    const int e0   = (blockIdx.x & 127) * MROWS;

    // ---- prologue: coalesced copy of precomputed B frags + bias ----
    {
        const uint4* src = (const uint4*)g_bfrag;
        uint4* dst = (uint4*)sBF;
        #pragma unroll
        for (int i = 0; i < NBF / 2 / THREADS; i++)      // 10 uint4 per thread
            dst[tid + i * THREADS] = src[tid + i * THREADS];
        if (tid < 256) sBI[tid] = g_bias[tid];
    }
    // ---- prologue: A = [x0 | h0-permuted] halfs ----
    for (int idx = tid; idx < MROWS * 80; idx += THREADS) {
        const int r = idx / 80, k = idx - r * 80;
        float v;
        if (k < 16) {
            float t0 = traj_rel[(e0 + r) * 2 + 0];
            float t1 = traj_rel[(e0 + r) * 2 + 1];
            v = lrelu_(t0 * We[k * 2 + 0] + t1 * We[k * 2 + 1] + be[k]);
        } else {
            const int j = k - 16;
            v = h0[(e0 + r) * HDIM + 4 * (j & 15) + (j >> 4)];
        }
        sAh[r * STRH + k] = __float2half_rn(v);
    }
    // Wp interleaved: sWp[u*2 + d] = Wp[m][d][u]
    if (tid < 128) sWp[tid] = Wp[m * 128 + (tid & 1) * 64 + (tid >> 1)];
    if (tid < 32)  sWe[tid] = We[tid];
    if (tid < 16)  sbe[tid] = be[tid];
    if (tid < 2)   sbp[tid] = bp[m * 2 + tid];

    // per-thread cell state: rows rA / rA+8, units u = 4q + tig, q = 0..15
    float ca[16], cb[16];
    #pragma unroll
    for (int q = 0; q < 16; q++) {
        ca[q] = c0[(e0 + rA) * HDIM + 4 * q + tig];
        cb[q] = c0[(e0 + rA + 8) * HDIM + 4 * q + tig];
    }

    __syncthreads();      // one-time: prologue visible to all warps

    const float bp0 = sbp[0], bp1 = sbp[1];
    float* hfa = g_hfin + ((size_t)m * NB + e0 + rA) * HDIM;        // final-h bases
    float* hfb = hfa + 8 * HDIM;

    // persistent fragments: af[0] = x-frag (registers across iterations)
    uint32_t af[KS][4];
    af[0][0] = *(const uint32_t*)(sAh + rA * STRH + 2 * tig);
    af[0][1] = *(const uint32_t*)(sAh + (rA + 8) * STRH + 2 * tig);
    af[0][2] = *(const uint32_t*)(sAh + rA * STRH + 2 * tig + 8);
    af[0][3] = *(const uint32_t*)(sAh + (rA + 8) * STRH + 2 * tig + 8);

    for (int t = 0; t < SEQ; t++) {
        // ---- load h fragments (ks = 1..4) from own warp's rows ----
        #pragma unroll
        for (int ks = 1; ks < KS; ks++) {
            const int k0 = ks * 16 + 2 * tig;
            af[ks][0] = *(const uint32_t*)(sAh + rA * STRH + k0);
            af[ks][1] = *(const uint32_t*)(sAh + (rA + 8) * STRH + k0);
            af[ks][2] = *(const uint32_t*)(sAh + rA * STRH + k0 + 8);
            af[ks][3] = *(const uint32_t*)(sAh + (rA + 8) * STRH + k0 + 8);
        }
        __syncwarp();   // loads complete before this iteration's h stores

        float p0a = 0.f, p1a = 0.f, p0b = 0.f, p1b = 0.f;

        // ---- 8 groups: tiles {T0, T0+1, 16+T0, 17+T0} = 4 chains ----
        #pragma unroll
        for (int qq = 0; qq < 8; qq++) {
            const int T0 = 2 * qq;
            float d[4][4];
            #pragma unroll
            for (int i = 0; i < 4; i++) {
                const int T = (i < 2) ? (T0 + i) : (16 + T0 + (i - 2));
                const float2 bv = *(const float2*)(sBI + T * 8 + 2 * tig);
                d[i][0] = bv.x; d[i][1] = bv.y; d[i][2] = bv.x; d[i][3] = bv.y;
            }
            #pragma unroll
            for (int ks = 0; ks < KS; ks++) {
                #pragma unroll
                for (int i = 0; i < 4; i++) {
                    const int T = (i < 2) ? (T0 + i) : (16 + T0 + (i - 2));
                    const uint2 bv = ((const uint2*)sBF)[(T * KS + ks) * 32 + lane];
                    mma16(d[i][0], d[i][1], d[i][2], d[i][3],
                          af[ks][0], af[ks][1], af[ks][2], af[ks][3],
                          bv.x, bv.y);
                }
            }
            // ---- epilogue: units u = 4*(2qq+j)+tig, rows rA and rA+8, no shfl ----
            float ha[2], hb[2];
            #pragma unroll
            for (int j = 0; j < 2; j++) {
                const int qi = 2 * qq + j;
                const int u  = 4 * qi + tig;
                const float2 wp2 = *(const float2*)(sWp + u * 2);
                {   // row rA: d[j] = (i,f), d[2+j] = (g,o), lanes 0,1
                    const float iv = sigf(d[j][0]);
                    const float fv = sigf(d[j][1]);
                    const float gv = tanha(d[2 + j][0]);
                    const float ov = sigf(d[2 + j][1]);
                    const float cn = fv * ca[qi] + iv * gv;
                    ca[qi] = cn;
                    const float h = ov * tanha(cn);
                    ha[j] = h;
                    p0a += h * wp2.x; p1a += h * wp2.y;
                }
                {   // row rA+8: lanes 2,3
                    const float iv = sigf(d[j][2]);
                    const float fv = sigf(d[j][3]);
                    const float gv = tanha(d[2 + j][2]);
                    const float ov = sigf(d[2 + j][3]);
                    const float cn = fv * cb[qi] + iv * gv;
                    cb[qi] = cn;
                    const float h = ov * tanha(cn);
                    hb[j] = h;
                    p0b += h * wp2.x; p1b += h * wp2.y;
                }
                if (t == SEQ - 1) {
                    hfa[u] = ha[j];
                    hfb[u] = hb[j];
                }
            }
            // h writeback: unit 4qi+tig -> col 16 + 16*tig + qi  (pairs qi=2qq,2qq+1)
            *(uint32_t*)(sAh + rA * STRH + 16 + 16 * tig + 2 * qq)       = packh2(ha[0], ha[1]);
            *(uint32_t*)(sAh + (rA + 8) * STRH + 16 + 16 * tig + 2 * qq) = packh2(hb[0], hb[1]);
        }

        // ---- rel_pos: reduce over tig within quad (units partition) ----
        p0a += __shfl_xor_sync(0xffffffffu, p0a, 1);
        p0a += __shfl_xor_sync(0xffffffffu, p0a, 2);
        p1a += __shfl_xor_sync(0xffffffffu, p1a, 1);
        p1a += __shfl_xor_sync(0xffffffffu, p1a, 2);
        p0b += __shfl_xor_sync(0xffffffffu, p0b, 1);
        p0b += __shfl_xor_sync(0xffffffffu, p0b, 2);
        p1b += __shfl_xor_sync(0xffffffffu, p1b, 1);
        p1b += __shfl_xor_sync(0xffffffffu, p1b, 2);
        const float ra0 = p0a + bp0, ra1 = p1a + bp1;   // rel_pos(rA)
        const float rb0 = p0b + bp0, rb1 = p1b + bp1;   // rel_pos(rA+8)
        if (tig < 2) {
            float2 rv = tig ? make_float2(rb0, rb1) : make_float2(ra0, ra1);
            *(float2*)(out + (size_t)(e0 + rA + 8 * tig) * (NMODE * SEQ * 2)
                           + m * (SEQ * 2) + t * 2) = rv;
        }
        // next x fragment: cols 2tig,2tig+1 (lo) and +8 (hi) for rows rA, rA+8
        {
            const int k0 = 2 * tig;
            #pragma unroll
            for (int hh = 0; hh < 2; hh++) {
                const int ka = k0 + 8 * hh, kb = ka + 1;
                const float xa0 = lrelu_(fmaf(ra0, sWe[ka * 2], fmaf(ra1, sWe[ka * 2 + 1], sbe[ka])));
                const float xa1 = lrelu_(fmaf(ra0, sWe[kb * 2], fmaf(ra1, sWe[kb * 2 + 1], sbe[kb])));
                const float xb0 = lrelu_(fmaf(rb0, sWe[ka * 2], fmaf(rb1, sWe[ka * 2 + 1], sbe[ka])));
                const float xb1 = lrelu_(fmaf(rb0, sWe[kb * 2], fmaf(rb1, sWe[kb * 2 + 1], sbe[kb])));
                af[0][0 + hh * 2] = packh2(xa0, xa1);
                af[0][1 + hh * 2] = packh2(xb0, xb1);
            }
        }
        __syncwarp();   // h stores visible before next iteration's loads
    }
}

// ============================ confidence kernel ============================
#define CONF_EPW 2
__global__ void __launch_bounds__(256)
conf_kernel(const float* __restrict__ Wc,
            const float* __restrict__ bc,
            float* __restrict__ out)
{
    const int warp  = (blockIdx.x * blockDim.x + threadIdx.x) >> 5;
    const int lane  = threadIdx.x & 31;
    const int ebase = warp * CONF_EPW;

    for (int ei = 0; ei < CONF_EPW; ei++) {
        const int e = ebase + ei;
        float l0 = 0.f, l1 = 0.f, l2 = 0.f;
        #pragma unroll
        for (int i = 0; i < 12; i++) {
            const int k = lane + 32 * i;
            if (k < 372) {
                const int q = (k >= 248) ? 2 : (k >= 124 ? 1 : 0);
                const int r = k - q * 124;
                const float v = (r < 60)
                    ? out[e * (NMODE * SEQ * 2) + q * 60 + r]
                    : g_hfin[(q * NB + e) * HDIM + (r - 60)];
                l0 += Wc[0 * 372 + k] * v;
                l1 += Wc[1 * 372 + k] * v;
                l2 += Wc[2 * 372 + k] * v;
            }
        }
        #pragma unroll
        for (int s = 16; s > 0; s >>= 1) {
            l0 += __shfl_xor_sync(0xffffffffu, l0, s);
            l1 += __shfl_xor_sync(0xffffffffu, l1, s);
            l2 += __shfl_xor_sync(0xffffffffu, l2, s);
        }
        if (lane == 0) {
            l0 += bc[0]; l1 += bc[1]; l2 += bc[2];
            const float mx = fmaxf(l0, fmaxf(l1, l2));
            const float x0 = __expf(l0 - mx), x1 = __expf(l1 - mx), x2 = __expf(l2 - mx);
            const float inv = __fdividef(1.0f, x0 + x1 + x2);
            float* cf = out + NB * (NMODE * SEQ * 2) + e * NMODE;
            cf[0] = x0 * inv; cf[1] = x1 * inv; cf[2] = x2 * inv;
        }
    }
}

extern "C" void kernel_launch(void* const* d_in, const int* in_sizes, int n_in,
                              void* d_out, int out_size)
{
    const float* traj_rel = (const float*)d_in[1];
    const float* h0   = (const float*)d_in[2];
    const float* c0   = (const float*)d_in[3];
    const float* W_ih = (const float*)d_in[4];
    const float* W_hh = (const float*)d_in[5];
    const float* b_ih = (const float*)d_in[6];
    const float* b_hh = (const float*)d_in[7];
    const float* We   = (const float*)d_in[8];
    const float* be   = (const float*)d_in[9];
    const float* Wp   = (const float*)d_in[10];
    const float* bp   = (const float*)d_in[11];
    const float* Wc   = (const float*)d_in[12];
    const float* bc   = (const float*)d_in[13];
    float* out = (float*)d_out;

    cudaFuncSetAttribute(lstm_mma,
                         cudaFuncAttributeMaxDynamicSharedMemorySize, SMEM_BYTES);

    prep_b<<<(NBF + 255) / 256, 256>>>(W_ih, W_hh, b_ih, b_hh);
    lstm_mma<<<NCTAS, THREADS, SMEM_BYTES>>>(traj_rel, h0, c0,
                                             We, be, Wp, bp, out);
    conf_kernel<<<NB / (CONF_EPW * 8), 256>>>(Wc, bc, out);
}